// round 13
// baseline (speedup 1.0000x reference)
#include <cuda_runtime.h>
#include <cuda_bf16.h>
#include <cstdint>

#define NN 50000
#define EE 300000
#define ETOT (EE + NN)          // edges + self loops
#define NEG_SLOPE 0.2f
#define EPS 1e-16f
#define SCAN_B 512
#define NBLK ((NN + SCAN_B - 1) / SCAN_B)   // 98 (co-resident on 148 SMs)
#define NCONV ((ETOT + 255) / 256)          // 1368 convert blocks
#define NGB2 ((NN + 127) / 128)             // 391 gemm2 blocks
#define OP 50048                            // padded node stride for o1T

typedef unsigned long long ull;

// ---------------- scratch (static device allocations only) ----------------
// INVARIANT: g_deg, g_pub, g_bar are zero at every kernel_launch entry.
__device__ int g_srcR[ETOT];
__device__ int g_dstR[ETOT];
__device__ int g_rank[ETOT];
__device__ int g_csr[ETOT];
__device__ int g_deg[NN];
__device__ int g_rs[NN + 1];
__device__ int g_pub[NBLK];
__device__ int g_bar;

__device__ float g_h1[NN * 256];
__device__ float g_ssrc1[NN * 4];
__device__ float g_sdst1[NN * 4];
__device__ float g_o1T[256 * OP];    // layer-1 ELU output, TRANSPOSED [k][node]
                                     // cols >= NN stay 0 (zero-init, never written)

__device__ float g_h2[NN * 128];
__device__ float g_ssrc2[NN * 2];
__device__ float g_sdst2[NN * 2];

// ---------------- helpers ----------------
__device__ __forceinline__ float lrelu(float x) {
    return x > 0.f ? x : NEG_SLOPE * x;
}
__device__ __forceinline__ float elu(float x) {
    return x > 0.f ? x : expm1f(x);
}
__device__ __forceinline__ ull pack2(float a, float b) {
    ull r; asm("mov.b64 %0,{%1,%2};" : "=l"(r) : "f"(a), "f"(b)); return r;
}
__device__ __forceinline__ void unpack2(ull p, float& a, float& b) {
    asm("mov.b64 {%0,%1},%2;" : "=f"(a), "=f"(b) : "l"(p));
}
__device__ __forceinline__ ull fma2(ull a, ull b, ull c) {
    ull d; asm("fma.rn.f32x2 %0,%1,%2,%3;" : "=l"(d) : "l"(a), "l"(b), "l"(c));
    return d;
}
__device__ __forceinline__ void cp_async16(unsigned int smem, const void* g) {
    asm volatile("cp.async.cg.shared.global [%0],[%1],16;" :: "r"(smem), "l"(g));
}
__device__ __forceinline__ void cp_commit() {
    asm volatile("cp.async.commit_group;");
}
__device__ __forceinline__ void cp_wait0() {
    asm volatile("cp.async.wait_group 0;" ::: "memory");
}

// ============ launch 0: edge convert + GEMM1+scores1 ========================
__global__ void __launch_bounds__(256) k_conv_gemm1s(
        const void* __restrict__ ei,
        const float* __restrict__ x, const float* __restrict__ W1,
        const float* __restrict__ a_src1, const float* __restrict__ a_dst1) {
    __shared__ __align__(16) float sxt[27 * 16];
    __shared__ __align__(16) float sh1[16 * 256];
    int tid = threadIdx.x;

    if (blockIdx.x < NCONV) {
        const int* ei32 = (const int*)ei;
        int probe = ei32[2 * tid + 1];
        int any = __syncthreads_or(probe);
        int is64 = (any == 0);
        int e = blockIdx.x * 256 + tid;
        if (e >= ETOT) return;
        int s, d;
        if (e >= EE) {
            s = d = e - EE;
        } else if (is64) {
            const long long* p = (const long long*)ei;
            s = (int)p[e]; d = (int)p[EE + e];
        } else {
            const int* p = (const int*)ei;
            s = p[e]; d = p[EE + e];
        }
        g_srcR[e] = s; g_dstR[e] = d;
        g_rank[e] = atomicAdd(&g_deg[d], 1);
        return;
    }

    int n0 = (blockIdx.x - NCONV) * 16;
    for (int i = tid; i < 27 * 16; i += 256) {
        int k = i >> 4, m = i & 15;
        sxt[i] = x[(n0 + m) * 27 + k];
    }
    float w[27];
#pragma unroll
    for (int k = 0; k < 27; k++) w[k] = W1[k * 256 + tid];
    __syncthreads();
    ull acc[8];
#pragma unroll
    for (int p = 0; p < 8; p++) acc[p] = 0ull;
#pragma unroll
    for (int k = 0; k < 27; k++) {
        ull wp = pack2(w[k], w[k]);
        const ulonglong2* xp = (const ulonglong2*)(sxt + k * 16);
#pragma unroll
        for (int q = 0; q < 4; q++) {
            ulonglong2 xv = xp[q];
            acc[2 * q]     = fma2(xv.x, wp, acc[2 * q]);
            acc[2 * q + 1] = fma2(xv.y, wp, acc[2 * q + 1]);
        }
    }
#pragma unroll
    for (int p = 0; p < 8; p++) {
        float lo, hi; unpack2(acc[p], lo, hi);
        g_h1[(size_t)(n0 + 2 * p) * 256 + tid] = lo;
        g_h1[(size_t)(n0 + 2 * p + 1) * 256 + tid] = hi;
        sh1[(2 * p) * 256 + tid] = lo;
        sh1[(2 * p + 1) * 256 + tid] = hi;
    }
    __syncthreads();

    int wrp = tid >> 5, lane = tid & 31;
    const float4* aS = (const float4*)a_src1;
    const float4* aD = (const float4*)a_dst1;
    float4 sA = aS[lane], sB = aS[32 + lane];
    float4 dA = aD[lane], dB = aD[32 + lane];
#pragma unroll
    for (int mi = 0; mi < 2; mi++) {
        int m = wrp * 2 + mi;
        const float4* hr = (const float4*)(sh1 + m * 256);
        float4 hA = hr[lane];
        float4 hB = hr[32 + lane];
        float psA = hA.x * sA.x + hA.y * sA.y + hA.z * sA.z + hA.w * sA.w;
        float pdA = hA.x * dA.x + hA.y * dA.y + hA.z * dA.z + hA.w * dA.w;
        float psB = hB.x * sB.x + hB.y * sB.y + hB.z * sB.z + hB.w * sB.w;
        float pdB = hB.x * dB.x + hB.y * dB.y + hB.z * dB.z + hB.w * dB.w;
#pragma unroll
        for (int o = 8; o; o >>= 1) {
            psA += __shfl_down_sync(0xFFFFFFFFu, psA, o);
            pdA += __shfl_down_sync(0xFFFFFFFFu, pdA, o);
            psB += __shfl_down_sync(0xFFFFFFFFu, psB, o);
            pdB += __shfl_down_sync(0xFFFFFFFFu, pdB, o);
        }
        int n = n0 + m;
        if (lane == 0) {
            g_ssrc1[n * 4 + 0] = psA; g_sdst1[n * 4 + 0] = pdA;
            g_ssrc1[n * 4 + 2] = psB; g_sdst1[n * 4 + 2] = pdB;
        }
        if (lane == 16) {
            g_ssrc1[n * 4 + 1] = psA; g_sdst1[n * 4 + 1] = pdA;
            g_ssrc1[n * 4 + 3] = psB; g_sdst1[n * 4 + 3] = pdB;
        }
    }
}

// ---------------- launch 1: scan (lookback) + grid barrier + scatter --------
__global__ void __launch_bounds__(SCAN_B) k_scan_scatter() {
    __shared__ int sh[SCAN_B];
    __shared__ int s_sum;
    int b = blockIdx.x, t = threadIdx.x;
    int i = b * SCAN_B + t;
    int v = (i < NN) ? g_deg[i] : 0;
    sh[t] = v;
    __syncthreads();
#pragma unroll
    for (int d = 1; d < SCAN_B; d <<= 1) {
        int u = (t >= d) ? sh[t - d] : 0;
        __syncthreads();
        sh[t] += u;
        __syncthreads();
    }
    int excl = sh[t] - v;
    int agg = sh[SCAN_B - 1];
    if (t == 0) {
        s_sum = 0;
        atomicExch(&g_pub[b], agg + 1);
    }
    __syncthreads();
    if (t < b) {
        int p;
        do { p = *(volatile int*)&g_pub[t]; } while (p == 0);
        atomicAdd(&s_sum, p - 1);
    }
    __syncthreads();
    if (i < NN) g_rs[i] = excl + s_sum;
    if (b == NBLK - 1 && t == SCAN_B - 1) g_rs[NN] = ETOT;

    __threadfence();
    __syncthreads();
    if (t == 0) {
        atomicAdd(&g_bar, 1);
        while (*(volatile int*)&g_bar < NBLK) {}
    }
    __syncthreads();
    __threadfence();

    for (int e = b * SCAN_B + t; e < ETOT; e += NBLK * SCAN_B) {
        int d = g_dstR[e];
        g_csr[g_rs[d] + g_rank[e]] = g_srcR[e];
    }
}

// ---------------- launch 2: layer-1 aggregation, warp / dst ----------------
// epilogue writes TRANSPOSED output o1T[k][node] via smem staging.
// grid is exactly 6250 blocks * 8 warps = 50000 nodes: no early-return warps.
__global__ void __launch_bounds__(256) k_agg1(const float* __restrict__ b1) {
    __shared__ __align__(16) float4 s_w4[8][32];
    __shared__ int s_si[8][32];
    __shared__ __align__(16) float s_out[8][256];   // staging for transpose
    int wid = (blockIdx.x * blockDim.x + threadIdx.x) >> 5;
    int wip = threadIdx.x >> 5;
    int lane = threadIdx.x & 31;
    int rs = g_rs[wid], re = g_rs[wid + 1];
    float4 sd = *(const float4*)(g_sdst1 + wid * 4);

    float4 mx = make_float4(-3.4e38f, -3.4e38f, -3.4e38f, -3.4e38f);
    for (int j = rs + lane; j < re; j += 32) {
        int s = g_csr[j];
        float4 ss = *(const float4*)(g_ssrc1 + s * 4);
        mx.x = fmaxf(mx.x, lrelu(ss.x + sd.x));
        mx.y = fmaxf(mx.y, lrelu(ss.y + sd.y));
        mx.z = fmaxf(mx.z, lrelu(ss.z + sd.z));
        mx.w = fmaxf(mx.w, lrelu(ss.w + sd.w));
    }
#pragma unroll
    for (int o = 16; o; o >>= 1) {
        mx.x = fmaxf(mx.x, __shfl_xor_sync(0xFFFFFFFFu, mx.x, o));
        mx.y = fmaxf(mx.y, __shfl_xor_sync(0xFFFFFFFFu, mx.y, o));
        mx.z = fmaxf(mx.z, __shfl_xor_sync(0xFFFFFFFFu, mx.z, o));
        mx.w = fmaxf(mx.w, __shfl_xor_sync(0xFFFFFFFFu, mx.w, o));
    }

    float4 zv = make_float4(0.f, 0.f, 0.f, 0.f);
    ull aL0 = 0, aL1 = 0, aH0 = 0, aH1 = 0;
    for (int base = rs; base < re; base += 32) {
        int cnt = min(32, re - base);
        int s_l = 0;
        float4 wv = make_float4(0.f, 0.f, 0.f, 0.f);
        if (lane < cnt) {
            s_l = g_csr[base + lane];
            float4 ss = *(const float4*)(g_ssrc1 + s_l * 4);
            wv.x = __expf(lrelu(ss.x + sd.x) - mx.x);
            wv.y = __expf(lrelu(ss.y + sd.y) - mx.y);
            wv.z = __expf(lrelu(ss.z + sd.z) - mx.z);
            wv.w = __expf(lrelu(ss.w + sd.w) - mx.w);
            zv.x += wv.x; zv.y += wv.y; zv.z += wv.z; zv.w += wv.w;
        }
        __syncwarp();
        s_w4[wip][lane] = wv;
        s_si[wip][lane] = s_l;
        __syncwarp();
        int t = 0;
        for (; t + 2 <= cnt; t += 2) {
            float4 w40 = s_w4[wip][t];
            float4 w41 = s_w4[wip][t + 1];
            int s0 = s_si[wip][t];
            int s1 = s_si[wip][t + 1];
            const ulonglong2* hp0 = (const ulonglong2*)(g_h1 + (size_t)s0 * 256);
            const ulonglong2* hp1 = (const ulonglong2*)(g_h1 + (size_t)s1 * 256);
            ulonglong2 l0 = hp0[lane], h0 = hp0[32 + lane];
            ulonglong2 l1 = hp1[lane], h1 = hp1[32 + lane];
            ull wa0 = pack2((lane < 16) ? w40.x : w40.y, (lane < 16) ? w40.x : w40.y);
            ull wb0 = pack2((lane < 16) ? w40.z : w40.w, (lane < 16) ? w40.z : w40.w);
            ull wa1 = pack2((lane < 16) ? w41.x : w41.y, (lane < 16) ? w41.x : w41.y);
            ull wb1 = pack2((lane < 16) ? w41.z : w41.w, (lane < 16) ? w41.z : w41.w);
            aL0 = fma2(l0.x, wa0, aL0); aL1 = fma2(l0.y, wa0, aL1);
            aH0 = fma2(h0.x, wb0, aH0); aH1 = fma2(h0.y, wb0, aH1);
            aL0 = fma2(l1.x, wa1, aL0); aL1 = fma2(l1.y, wa1, aL1);
            aH0 = fma2(h1.x, wb1, aH0); aH1 = fma2(h1.y, wb1, aH1);
        }
        if (t < cnt) {
            float4 w40 = s_w4[wip][t];
            int s0 = s_si[wip][t];
            const ulonglong2* hp0 = (const ulonglong2*)(g_h1 + (size_t)s0 * 256);
            ulonglong2 l0 = hp0[lane], h0 = hp0[32 + lane];
            ull wa0 = pack2((lane < 16) ? w40.x : w40.y, (lane < 16) ? w40.x : w40.y);
            ull wb0 = pack2((lane < 16) ? w40.z : w40.w, (lane < 16) ? w40.z : w40.w);
            aL0 = fma2(l0.x, wa0, aL0); aL1 = fma2(l0.y, wa0, aL1);
            aH0 = fma2(h0.x, wb0, aH0); aH1 = fma2(h0.y, wb0, aH1);
        }
    }
#pragma unroll
    for (int o = 16; o; o >>= 1) {
        zv.x += __shfl_xor_sync(0xFFFFFFFFu, zv.x, o);
        zv.y += __shfl_xor_sync(0xFFFFFFFFu, zv.y, o);
        zv.z += __shfl_xor_sync(0xFFFFFFFFu, zv.z, o);
        zv.w += __shfl_xor_sync(0xFFFFFFFFu, zv.w, o);
    }
    float ia = __fdividef(1.f, ((lane < 16) ? zv.x : zv.y) + EPS);
    float ib = __fdividef(1.f, ((lane < 16) ? zv.z : zv.w) + EPS);
    float4 accLo, accHi;
    unpack2(aL0, accLo.x, accLo.y); unpack2(aL1, accLo.z, accLo.w);
    unpack2(aH0, accHi.x, accHi.y); unpack2(aH1, accHi.z, accHi.w);
    float4 bLo = *(const float4*)(b1 + lane * 4);
    float4 bHi = *(const float4*)(b1 + 128 + lane * 4);
    float4 v;
    v.x = elu(fmaf(accLo.x, ia, bLo.x));
    v.y = elu(fmaf(accLo.y, ia, bLo.y));
    v.z = elu(fmaf(accLo.z, ia, bLo.z));
    v.w = elu(fmaf(accLo.w, ia, bLo.w));
    *(float4*)&s_out[wip][lane * 4] = v;
    v.x = elu(fmaf(accHi.x, ib, bHi.x));
    v.y = elu(fmaf(accHi.y, ib, bHi.y));
    v.z = elu(fmaf(accHi.z, ib, bHi.z));
    v.w = elu(fmaf(accHi.w, ib, bHi.w));
    *(float4*)&s_out[wip][128 + lane * 4] = v;
    __syncthreads();

    // transposed writeback: thread t owns feature k=t, writes 8 node-values
    int nb0 = blockIdx.x * 8;
    int k = threadIdx.x;
    float vals[8];
#pragma unroll
    for (int n = 0; n < 8; n++) vals[n] = s_out[n][k];
    float4* dst = (float4*)(g_o1T + (size_t)k * OP + nb0);
    dst[0] = make_float4(vals[0], vals[1], vals[2], vals[3]);
    dst[1] = make_float4(vals[4], vals[5], vals[6], vals[7]);
}

// ---------------- launch 3: GEMM2 (cp.async double-buffered) + scores2 ------
// 128x128 tile/block, 256 threads as 16x16, 8x8 register tile,
// K staged in 16-deep smem chunks, double-buffered via cp.async.
__global__ void __launch_bounds__(256, 2) k_gemm2s(const float* __restrict__ W2,
                                                   const float* __restrict__ a_src2,
                                                   const float* __restrict__ a_dst2) {
    __shared__ __align__(16) float sA[2][16][128];   // o1T chunk [kk][node]
    __shared__ __align__(16) float sB[2][16][128];   // W2 chunk  [kk][col]
    int tid = threadIdx.x;
    int tx = tid & 15;
    int ty = tid >> 4;
    int n0 = blockIdx.x * 128;
    int nvalid = min(128, NN - n0);

    unsigned int sa_u = (unsigned int)__cvta_generic_to_shared(&sA[0][0][0]);
    unsigned int sb_u = (unsigned int)__cvta_generic_to_shared(&sB[0][0][0]);

    // load 16-row chunk ck into buffer buf (2 x 16B per array per thread)
    auto load_chunk = [&](int ck, int buf) {
#pragma unroll
        for (int r = 0; r < 2; r++) {
            int i = tid + 256 * r;                 // 0..511
            int kk = i >> 5, seg = i & 31;
            cp_async16(sa_u + (unsigned int)(buf * 2048 + kk * 128 + seg * 4) * 4,
                       g_o1T + (size_t)(ck * 16 + kk) * OP + n0 + seg * 4);
            cp_async16(sb_u + (unsigned int)(buf * 2048 + kk * 128 + seg * 4) * 4,
                       W2 + (size_t)(ck * 16 + kk) * 128 + seg * 4);
        }
        cp_commit();
    };

    ull acc[8][4];
#pragma unroll
    for (int c = 0; c < 8; c++)
#pragma unroll
        for (int p = 0; p < 4; p++) acc[c][p] = 0ull;

    load_chunk(0, 0);
    for (int ck = 0; ck < 16; ck++) {
        cp_wait0();
        __syncthreads();
        if (ck < 15) load_chunk(ck + 1, (ck + 1) & 1);
        int buf = ck & 1;
#pragma unroll
        for (int kk = 0; kk < 16; kk++) {
            ulonglong2 a01 = *(const ulonglong2*)&sA[buf][kk][8 * ty];
            ulonglong2 a23 = *(const ulonglong2*)&sA[buf][kk][8 * ty + 4];
            float4 b0 = *(const float4*)&sB[buf][kk][8 * tx];
            float4 b1 = *(const float4*)&sB[buf][kk][8 * tx + 4];
            ull pb0 = pack2(b0.x, b0.x), pb1 = pack2(b0.y, b0.y);
            ull pb2 = pack2(b0.z, b0.z), pb3 = pack2(b0.w, b0.w);
            ull pb4 = pack2(b1.x, b1.x), pb5 = pack2(b1.y, b1.y);
            ull pb6 = pack2(b1.z, b1.z), pb7 = pack2(b1.w, b1.w);
            acc[0][0] = fma2(a01.x, pb0, acc[0][0]);
            acc[0][1] = fma2(a01.y, pb0, acc[0][1]);
            acc[0][2] = fma2(a23.x, pb0, acc[0][2]);
            acc[0][3] = fma2(a23.y, pb0, acc[0][3]);
            acc[1][0] = fma2(a01.x, pb1, acc[1][0]);
            acc[1][1] = fma2(a01.y, pb1, acc[1][1]);
            acc[1][2] = fma2(a23.x, pb1, acc[1][2]);
            acc[1][3] = fma2(a23.y, pb1, acc[1][3]);
            acc[2][0] = fma2(a01.x, pb2, acc[2][0]);
            acc[2][1] = fma2(a01.y, pb2, acc[2][1]);
            acc[2][2] = fma2(a23.x, pb2, acc[2][2]);
            acc[2][3] = fma2(a23.y, pb2, acc[2][3]);
            acc[3][0] = fma2(a01.x, pb3, acc[3][0]);
            acc[3][1] = fma2(a01.y, pb3, acc[3][1]);
            acc[3][2] = fma2(a23.x, pb3, acc[3][2]);
            acc[3][3] = fma2(a23.y, pb3, acc[3][3]);
            acc[4][0] = fma2(a01.x, pb4, acc[4][0]);
            acc[4][1] = fma2(a01.y, pb4, acc[4][1]);
            acc[4][2] = fma2(a23.x, pb4, acc[4][2]);
            acc[4][3] = fma2(a23.y, pb4, acc[4][3]);
            acc[5][0] = fma2(a01.x, pb5, acc[5][0]);
            acc[5][1] = fma2(a01.y, pb5, acc[5][1]);
            acc[5][2] = fma2(a23.x, pb5, acc[5][2]);
            acc[5][3] = fma2(a23.y, pb5, acc[5][3]);
            acc[6][0] = fma2(a01.x, pb6, acc[6][0]);
            acc[6][1] = fma2(a01.y, pb6, acc[6][1]);
            acc[6][2] = fma2(a23.x, pb6, acc[6][2]);
            acc[6][3] = fma2(a23.y, pb6, acc[6][3]);
            acc[7][0] = fma2(a01.x, pb7, acc[7][0]);
            acc[7][1] = fma2(a01.y, pb7, acc[7][1]);
            acc[7][2] = fma2(a23.x, pb7, acc[7][2]);
            acc[7][3] = fma2(a23.y, pb7, acc[7][3]);
        }
        __syncthreads();
    }

    // epilogue: write h2 tile + fused scores2 partials
    int head = tx >> 3;
    int off = (8 * tx) & 63;
    float4 as0 = *(const float4*)(a_src2 + head * 64 + off);
    float4 as1 = *(const float4*)(a_src2 + head * 64 + off + 4);
    float4 ad0 = *(const float4*)(a_dst2 + head * 64 + off);
    float4 ad1 = *(const float4*)(a_dst2 + head * 64 + off + 4);
    float asv[8] = {as0.x, as0.y, as0.z, as0.w, as1.x, as1.y, as1.z, as1.w};
    float adv[8] = {ad0.x, ad0.y, ad0.z, ad0.w, ad1.x, ad1.y, ad1.z, ad1.w};
    float ps[8], pd[8];
#pragma unroll
    for (int i = 0; i < 8; i++) { ps[i] = 0.f; pd[i] = 0.f; }

#pragma unroll
    for (int p = 0; p < 4; p++) {
        float v0[8], v1[8];
#pragma unroll
        for (int c = 0; c < 8; c++) unpack2(acc[c][p], v0[c], v1[c]);
#pragma unroll
        for (int c = 0; c < 8; c++) {
            ps[2 * p]     = fmaf(v0[c], asv[c], ps[2 * p]);
            pd[2 * p]     = fmaf(v0[c], adv[c], pd[2 * p]);
            ps[2 * p + 1] = fmaf(v1[c], asv[c], ps[2 * p + 1]);
            pd[2 * p + 1] = fmaf(v1[c], adv[c], pd[2 * p + 1]);
        }
        int nl0 = 8 * ty + 2 * p;
        if (nl0 < nvalid) {
            float* dst = g_h2 + (size_t)(n0 + nl0) * 128 + 8 * tx;
            *(float4*)dst       = make_float4(v0[0], v0[1], v0[2], v0[3]);
            *(float4*)(dst + 4) = make_float4(v0[4], v0[5], v0[6], v0[7]);
        }
        if (nl0 + 1 < nvalid) {
            float* dst = g_h2 + (size_t)(n0 + nl0 + 1) * 128 + 8 * tx;
            *(float4*)dst       = make_float4(v1[0], v1[1], v1[2], v1[3]);
            *(float4*)(dst + 4) = make_float4(v1[4], v1[5], v1[6], v1[7]);
        }
    }
#pragma unroll
    for (int o = 4; o; o >>= 1) {
#pragma unroll
        for (int i = 0; i < 8; i++) {
            ps[i] += __shfl_down_sync(0xFFFFFFFFu, ps[i], o);
            pd[i] += __shfl_down_sync(0xFFFFFFFFu, pd[i], o);
        }
    }
    if ((tx & 7) == 0) {
#pragma unroll
        for (int i = 0; i < 8; i++) {
            int nl = 8 * ty + i;
            if (nl < nvalid) {
                g_ssrc2[(n0 + nl) * 2 + head] = ps[i];
                g_sdst2[(n0 + nl) * 2 + head] = pd[i];
            }
        }
    }
}

// ---------------- launch 4: layer-2 aggregation + FC + sigmoid --------------
__global__ void __launch_bounds__(256) k_agg2(const float* __restrict__ b2,
                                              const float* __restrict__ Wfc,
                                              const float* __restrict__ bfc,
                                              float* __restrict__ out) {
    __shared__ __align__(8) float2 s_w2[8][32];
    __shared__ int s_si[8][32];
    int t0 = blockIdx.x * blockDim.x + threadIdx.x;
    if (t0 < NN) g_deg[t0] = 0;
    if (t0 < NBLK) g_pub[t0] = 0;
    if (t0 == 0) g_bar = 0;

    int wid = t0 >> 5;
    if (wid >= NN) return;
    int wip = threadIdx.x >> 5;
    int lane = threadIdx.x & 31;
    int rs = g_rs[wid], re = g_rs[wid + 1];
    float2 sd = *(const float2*)(g_sdst2 + wid * 2);

    float2 mx = make_float2(-3.4e38f, -3.4e38f);
    for (int j = rs + lane; j < re; j += 32) {
        int s = g_csr[j];
        float2 ss = *(const float2*)(g_ssrc2 + s * 2);
        mx.x = fmaxf(mx.x, lrelu(ss.x + sd.x));
        mx.y = fmaxf(mx.y, lrelu(ss.y + sd.y));
    }
#pragma unroll
    for (int o = 16; o; o >>= 1) {
        mx.x = fmaxf(mx.x, __shfl_xor_sync(0xFFFFFFFFu, mx.x, o));
        mx.y = fmaxf(mx.y, __shfl_xor_sync(0xFFFFFFFFu, mx.y, o));
    }

    float2 zv = make_float2(0.f, 0.f);
    ull a0 = 0, a1 = 0;
    for (int base = rs; base < re; base += 32) {
        int cnt = min(32, re - base);
        int s_l = 0;
        float2 wv = make_float2(0.f, 0.f);
        if (lane < cnt) {
            s_l = g_csr[base + lane];
            float2 ss = *(const float2*)(g_ssrc2 + s_l * 2);
            wv.x = __expf(lrelu(ss.x + sd.x) - mx.x);
            wv.y = __expf(lrelu(ss.y + sd.y) - mx.y);
            zv.x += wv.x; zv.y += wv.y;
        }
        __syncwarp();
        s_w2[wip][lane] = wv;
        s_si[wip][lane] = s_l;
        __syncwarp();
        int t = 0;
        for (; t + 2 <= cnt; t += 2) {
            float2 w20 = s_w2[wip][t];
            float2 w21 = s_w2[wip][t + 1];
            int s0 = s_si[wip][t];
            int s1 = s_si[wip][t + 1];
            const ulonglong2* hp0 = (const ulonglong2*)(g_h2 + (size_t)s0 * 128);
            const ulonglong2* hp1 = (const ulonglong2*)(g_h2 + (size_t)s1 * 128);
            ulonglong2 h0 = hp0[lane];
            ulonglong2 h1 = hp1[lane];
            float wa0 = (lane < 16) ? w20.x : w20.y;
            float wa1 = (lane < 16) ? w21.x : w21.y;
            ull wp0 = pack2(wa0, wa0);
            ull wp1 = pack2(wa1, wa1);
            a0 = fma2(h0.x, wp0, a0); a1 = fma2(h0.y, wp0, a1);
            a0 = fma2(h1.x, wp1, a0); a1 = fma2(h1.y, wp1, a1);
        }
        if (t < cnt) {
            float2 w20 = s_w2[wip][t];
            int s0 = s_si[wip][t];
            const ulonglong2* hp0 = (const ulonglong2*)(g_h2 + (size_t)s0 * 128);
            ulonglong2 h0 = hp0[lane];
            float wa0 = (lane < 16) ? w20.x : w20.y;
            ull wp0 = pack2(wa0, wa0);
            a0 = fma2(h0.x, wp0, a0); a1 = fma2(h0.y, wp0, a1);
        }
    }
#pragma unroll
    for (int o = 16; o; o >>= 1) {
        zv.x += __shfl_xor_sync(0xFFFFFFFFu, zv.x, o);
        zv.y += __shfl_xor_sync(0xFFFFFFFFu, zv.y, o);
    }
    float iz = __fdividef(1.f, ((lane < 16) ? zv.x : zv.y) + EPS);
    float4 acc;
    unpack2(a0, acc.x, acc.y); unpack2(a1, acc.z, acc.w);
    float4 b = *(const float4*)(b2 + lane * 4);
    float4 wf = *(const float4*)(Wfc + lane * 4);
    float t = elu(fmaf(acc.x, iz, b.x)) * wf.x
            + elu(fmaf(acc.y, iz, b.y)) * wf.y
            + elu(fmaf(acc.z, iz, b.z)) * wf.z
            + elu(fmaf(acc.w, iz, b.w)) * wf.w;
#pragma unroll
    for (int o = 16; o; o >>= 1) t += __shfl_down_sync(0xFFFFFFFFu, t, o);
    if (lane == 0) {
        float s = t + bfc[0];
        out[wid] = __fdividef(1.f, 1.f + __expf(-s));
    }
}

// ---------------- launch ----------------
extern "C" void kernel_launch(void* const* d_in, const int* in_sizes, int n_in,
                              void* d_out, int out_size) {
    const float* x      = (const float*)d_in[0];
    const void*  ei     = d_in[1];
    const float* W1     = (const float*)d_in[2];
    const float* a_src1 = (const float*)d_in[3];
    const float* a_dst1 = (const float*)d_in[4];
    const float* b1     = (const float*)d_in[5];
    const float* W2     = (const float*)d_in[6];
    const float* a_src2 = (const float*)d_in[7];
    const float* a_dst2 = (const float*)d_in[8];
    const float* b2     = (const float*)d_in[9];
    const float* Wfc    = (const float*)d_in[10];
    const float* bfc    = (const float*)d_in[11];
    float* out = (float*)d_out;

    k_conv_gemm1s<<<NCONV + NN / 16, 256>>>(ei, x, W1, a_src1, a_dst1); // 0
    k_scan_scatter<<<NBLK, SCAN_B>>>();                                // 1
    k_agg1<<<(NN + 7) / 8, 256>>>(b1);                                 // 2
    k_gemm2s<<<NGB2, 256>>>(W2, a_src2, a_dst2);                       // 3 <- ncu
    k_agg2<<<(NN + 7) / 8, 256>>>(b2, Wfc, bfc, out);                  // 4
}

// round 14
// speedup vs baseline: 1.0446x; 1.0446x over previous
#include <cuda_runtime.h>
#include <cuda_bf16.h>
#include <cstdint>

#define NN 50000
#define EE 300000
#define ETOT (EE + NN)          // edges + self loops
#define NEG_SLOPE 0.2f
#define EPS 1e-16f
#define SCAN_B 512
#define NBLK ((NN + SCAN_B - 1) / SCAN_B)   // 98 (co-resident on 148 SMs)
#define NCONV ((ETOT + 255) / 256)          // 1368 convert blocks
#define NGB2 ((NN + 127) / 128)             // 391 gemm2 blocks
#define OP 50048                            // padded node stride for o1T

typedef unsigned long long ull;

// ---------------- scratch (static device allocations only) ----------------
// INVARIANT: g_deg, g_pub, g_bar are zero at every kernel_launch entry.
__device__ int g_srcR[ETOT];
__device__ int g_dstR[ETOT];
__device__ int g_rank[ETOT];
__device__ int g_csr[ETOT];
__device__ int g_deg[NN];
__device__ int g_rs[NN + 1];
__device__ int g_pub[NBLK];
__device__ int g_bar;

__device__ float g_h1[NN * 256];
__device__ float g_ssrc1[NN * 4];
__device__ float g_sdst1[NN * 4];
__device__ float g_o1T[256 * OP];    // layer-1 ELU output, TRANSPOSED [k][node]
                                     // cols >= NN stay 0 (zero-init, never written)

__device__ float g_h2[NN * 128];
__device__ float g_ssrc2[NN * 2];
__device__ float g_sdst2[NN * 2];

// ---------------- helpers ----------------
__device__ __forceinline__ float lrelu(float x) {
    return x > 0.f ? x : NEG_SLOPE * x;
}
__device__ __forceinline__ float elu(float x) {
    return x > 0.f ? x : expm1f(x);
}
__device__ __forceinline__ ull pack2(float a, float b) {
    ull r; asm("mov.b64 %0,{%1,%2};" : "=l"(r) : "f"(a), "f"(b)); return r;
}
__device__ __forceinline__ void unpack2(ull p, float& a, float& b) {
    asm("mov.b64 {%0,%1},%2;" : "=f"(a), "=f"(b) : "l"(p));
}
__device__ __forceinline__ ull fma2(ull a, ull b, ull c) {
    ull d; asm("fma.rn.f32x2 %0,%1,%2,%3;" : "=l"(d) : "l"(a), "l"(b), "l"(c));
    return d;
}
__device__ __forceinline__ void cp_async16(unsigned int smem, const void* g) {
    asm volatile("cp.async.cg.shared.global [%0],[%1],16;" :: "r"(smem), "l"(g));
}
__device__ __forceinline__ void cp_commit() {
    asm volatile("cp.async.commit_group;");
}
__device__ __forceinline__ void cp_wait0() {
    asm volatile("cp.async.wait_group 0;" ::: "memory");
}

// ============ launch 0: edge convert + GEMM1+scores1 ========================
__global__ void __launch_bounds__(256) k_conv_gemm1s(
        const void* __restrict__ ei,
        const float* __restrict__ x, const float* __restrict__ W1,
        const float* __restrict__ a_src1, const float* __restrict__ a_dst1) {
    __shared__ __align__(16) float sxt[27 * 16];
    __shared__ __align__(16) float sh1[16 * 256];
    int tid = threadIdx.x;

    if (blockIdx.x < NCONV) {
        const int* ei32 = (const int*)ei;
        int probe = ei32[2 * tid + 1];
        int any = __syncthreads_or(probe);
        int is64 = (any == 0);
        int e = blockIdx.x * 256 + tid;
        if (e >= ETOT) return;
        int s, d;
        if (e >= EE) {
            s = d = e - EE;
        } else if (is64) {
            const long long* p = (const long long*)ei;
            s = (int)p[e]; d = (int)p[EE + e];
        } else {
            const int* p = (const int*)ei;
            s = p[e]; d = p[EE + e];
        }
        g_srcR[e] = s; g_dstR[e] = d;
        g_rank[e] = atomicAdd(&g_deg[d], 1);
        return;
    }

    int n0 = (blockIdx.x - NCONV) * 16;
    for (int i = tid; i < 27 * 16; i += 256) {
        int k = i >> 4, m = i & 15;
        sxt[i] = x[(n0 + m) * 27 + k];
    }
    float w[27];
#pragma unroll
    for (int k = 0; k < 27; k++) w[k] = W1[k * 256 + tid];
    __syncthreads();
    ull acc[8];
#pragma unroll
    for (int p = 0; p < 8; p++) acc[p] = 0ull;
#pragma unroll
    for (int k = 0; k < 27; k++) {
        ull wp = pack2(w[k], w[k]);
        const ulonglong2* xp = (const ulonglong2*)(sxt + k * 16);
#pragma unroll
        for (int q = 0; q < 4; q++) {
            ulonglong2 xv = xp[q];
            acc[2 * q]     = fma2(xv.x, wp, acc[2 * q]);
            acc[2 * q + 1] = fma2(xv.y, wp, acc[2 * q + 1]);
        }
    }
#pragma unroll
    for (int p = 0; p < 8; p++) {
        float lo, hi; unpack2(acc[p], lo, hi);
        g_h1[(size_t)(n0 + 2 * p) * 256 + tid] = lo;
        g_h1[(size_t)(n0 + 2 * p + 1) * 256 + tid] = hi;
        sh1[(2 * p) * 256 + tid] = lo;
        sh1[(2 * p + 1) * 256 + tid] = hi;
    }
    __syncthreads();

    int wrp = tid >> 5, lane = tid & 31;
    const float4* aS = (const float4*)a_src1;
    const float4* aD = (const float4*)a_dst1;
    float4 sA = aS[lane], sB = aS[32 + lane];
    float4 dA = aD[lane], dB = aD[32 + lane];
#pragma unroll
    for (int mi = 0; mi < 2; mi++) {
        int m = wrp * 2 + mi;
        const float4* hr = (const float4*)(sh1 + m * 256);
        float4 hA = hr[lane];
        float4 hB = hr[32 + lane];
        float psA = hA.x * sA.x + hA.y * sA.y + hA.z * sA.z + hA.w * sA.w;
        float pdA = hA.x * dA.x + hA.y * dA.y + hA.z * dA.z + hA.w * dA.w;
        float psB = hB.x * sB.x + hB.y * sB.y + hB.z * sB.z + hB.w * sB.w;
        float pdB = hB.x * dB.x + hB.y * dB.y + hB.z * dB.z + hB.w * dB.w;
#pragma unroll
        for (int o = 8; o; o >>= 1) {
            psA += __shfl_down_sync(0xFFFFFFFFu, psA, o);
            pdA += __shfl_down_sync(0xFFFFFFFFu, pdA, o);
            psB += __shfl_down_sync(0xFFFFFFFFu, psB, o);
            pdB += __shfl_down_sync(0xFFFFFFFFu, pdB, o);
        }
        int n = n0 + m;
        if (lane == 0) {
            g_ssrc1[n * 4 + 0] = psA; g_sdst1[n * 4 + 0] = pdA;
            g_ssrc1[n * 4 + 2] = psB; g_sdst1[n * 4 + 2] = pdB;
        }
        if (lane == 16) {
            g_ssrc1[n * 4 + 1] = psA; g_sdst1[n * 4 + 1] = pdA;
            g_ssrc1[n * 4 + 3] = psB; g_sdst1[n * 4 + 3] = pdB;
        }
    }
}

// ---------------- launch 1: scan (lookback) + grid barrier + scatter --------
__global__ void __launch_bounds__(SCAN_B) k_scan_scatter() {
    __shared__ int sh[SCAN_B];
    __shared__ int s_sum;
    int b = blockIdx.x, t = threadIdx.x;
    int i = b * SCAN_B + t;
    int v = (i < NN) ? g_deg[i] : 0;
    sh[t] = v;
    __syncthreads();
#pragma unroll
    for (int d = 1; d < SCAN_B; d <<= 1) {
        int u = (t >= d) ? sh[t - d] : 0;
        __syncthreads();
        sh[t] += u;
        __syncthreads();
    }
    int excl = sh[t] - v;
    int agg = sh[SCAN_B - 1];
    if (t == 0) {
        s_sum = 0;
        atomicExch(&g_pub[b], agg + 1);
    }
    __syncthreads();
    if (t < b) {
        int p;
        do { p = *(volatile int*)&g_pub[t]; } while (p == 0);
        atomicAdd(&s_sum, p - 1);
    }
    __syncthreads();
    if (i < NN) g_rs[i] = excl + s_sum;
    if (b == NBLK - 1 && t == SCAN_B - 1) g_rs[NN] = ETOT;

    __threadfence();
    __syncthreads();
    if (t == 0) {
        atomicAdd(&g_bar, 1);
        while (*(volatile int*)&g_bar < NBLK) {}
    }
    __syncthreads();
    __threadfence();

    for (int e = b * SCAN_B + t; e < ETOT; e += NBLK * SCAN_B) {
        int d = g_dstR[e];
        g_csr[g_rs[d] + g_rank[e]] = g_srcR[e];
    }
}

// ---------------- launch 2: layer-1 aggregation, warp / dst ----------------
// epilogue writes TRANSPOSED output o1T[k][node] via smem staging.
__global__ void __launch_bounds__(256) k_agg1(const float* __restrict__ b1) {
    __shared__ __align__(16) float4 s_w4[8][32];
    __shared__ int s_si[8][32];
    __shared__ __align__(16) float s_out[8][256];   // staging for transpose
    int wid = (blockIdx.x * blockDim.x + threadIdx.x) >> 5;
    int wip = threadIdx.x >> 5;
    int lane = threadIdx.x & 31;
    int rs = g_rs[wid], re = g_rs[wid + 1];
    float4 sd = *(const float4*)(g_sdst1 + wid * 4);

    float4 mx = make_float4(-3.4e38f, -3.4e38f, -3.4e38f, -3.4e38f);
    for (int j = rs + lane; j < re; j += 32) {
        int s = g_csr[j];
        float4 ss = *(const float4*)(g_ssrc1 + s * 4);
        mx.x = fmaxf(mx.x, lrelu(ss.x + sd.x));
        mx.y = fmaxf(mx.y, lrelu(ss.y + sd.y));
        mx.z = fmaxf(mx.z, lrelu(ss.z + sd.z));
        mx.w = fmaxf(mx.w, lrelu(ss.w + sd.w));
    }
#pragma unroll
    for (int o = 16; o; o >>= 1) {
        mx.x = fmaxf(mx.x, __shfl_xor_sync(0xFFFFFFFFu, mx.x, o));
        mx.y = fmaxf(mx.y, __shfl_xor_sync(0xFFFFFFFFu, mx.y, o));
        mx.z = fmaxf(mx.z, __shfl_xor_sync(0xFFFFFFFFu, mx.z, o));
        mx.w = fmaxf(mx.w, __shfl_xor_sync(0xFFFFFFFFu, mx.w, o));
    }

    float4 zv = make_float4(0.f, 0.f, 0.f, 0.f);
    ull aL0 = 0, aL1 = 0, aH0 = 0, aH1 = 0;
    for (int base = rs; base < re; base += 32) {
        int cnt = min(32, re - base);
        int s_l = 0;
        float4 wv = make_float4(0.f, 0.f, 0.f, 0.f);
        if (lane < cnt) {
            s_l = g_csr[base + lane];
            float4 ss = *(const float4*)(g_ssrc1 + s_l * 4);
            wv.x = __expf(lrelu(ss.x + sd.x) - mx.x);
            wv.y = __expf(lrelu(ss.y + sd.y) - mx.y);
            wv.z = __expf(lrelu(ss.z + sd.z) - mx.z);
            wv.w = __expf(lrelu(ss.w + sd.w) - mx.w);
            zv.x += wv.x; zv.y += wv.y; zv.z += wv.z; zv.w += wv.w;
        }
        __syncwarp();
        s_w4[wip][lane] = wv;
        s_si[wip][lane] = s_l;
        __syncwarp();
        int t = 0;
        for (; t + 2 <= cnt; t += 2) {
            float4 w40 = s_w4[wip][t];
            float4 w41 = s_w4[wip][t + 1];
            int s0 = s_si[wip][t];
            int s1 = s_si[wip][t + 1];
            const ulonglong2* hp0 = (const ulonglong2*)(g_h1 + (size_t)s0 * 256);
            const ulonglong2* hp1 = (const ulonglong2*)(g_h1 + (size_t)s1 * 256);
            ulonglong2 l0 = hp0[lane], h0 = hp0[32 + lane];
            ulonglong2 l1 = hp1[lane], h1 = hp1[32 + lane];
            ull wa0 = pack2((lane < 16) ? w40.x : w40.y, (lane < 16) ? w40.x : w40.y);
            ull wb0 = pack2((lane < 16) ? w40.z : w40.w, (lane < 16) ? w40.z : w40.w);
            ull wa1 = pack2((lane < 16) ? w41.x : w41.y, (lane < 16) ? w41.x : w41.y);
            ull wb1 = pack2((lane < 16) ? w41.z : w41.w, (lane < 16) ? w41.z : w41.w);
            aL0 = fma2(l0.x, wa0, aL0); aL1 = fma2(l0.y, wa0, aL1);
            aH0 = fma2(h0.x, wb0, aH0); aH1 = fma2(h0.y, wb0, aH1);
            aL0 = fma2(l1.x, wa1, aL0); aL1 = fma2(l1.y, wa1, aL1);
            aH0 = fma2(h1.x, wb1, aH0); aH1 = fma2(h1.y, wb1, aH1);
        }
        if (t < cnt) {
            float4 w40 = s_w4[wip][t];
            int s0 = s_si[wip][t];
            const ulonglong2* hp0 = (const ulonglong2*)(g_h1 + (size_t)s0 * 256);
            ulonglong2 l0 = hp0[lane], h0 = hp0[32 + lane];
            ull wa0 = pack2((lane < 16) ? w40.x : w40.y, (lane < 16) ? w40.x : w40.y);
            ull wb0 = pack2((lane < 16) ? w40.z : w40.w, (lane < 16) ? w40.z : w40.w);
            aL0 = fma2(l0.x, wa0, aL0); aL1 = fma2(l0.y, wa0, aL1);
            aH0 = fma2(h0.x, wb0, aH0); aH1 = fma2(h0.y, wb0, aH1);
        }
    }
#pragma unroll
    for (int o = 16; o; o >>= 1) {
        zv.x += __shfl_xor_sync(0xFFFFFFFFu, zv.x, o);
        zv.y += __shfl_xor_sync(0xFFFFFFFFu, zv.y, o);
        zv.z += __shfl_xor_sync(0xFFFFFFFFu, zv.z, o);
        zv.w += __shfl_xor_sync(0xFFFFFFFFu, zv.w, o);
    }
    float ia = __fdividef(1.f, ((lane < 16) ? zv.x : zv.y) + EPS);
    float ib = __fdividef(1.f, ((lane < 16) ? zv.z : zv.w) + EPS);
    float4 accLo, accHi;
    unpack2(aL0, accLo.x, accLo.y); unpack2(aL1, accLo.z, accLo.w);
    unpack2(aH0, accHi.x, accHi.y); unpack2(aH1, accHi.z, accHi.w);
    float4 bLo = *(const float4*)(b1 + lane * 4);
    float4 bHi = *(const float4*)(b1 + 128 + lane * 4);
    float4 v;
    v.x = elu(fmaf(accLo.x, ia, bLo.x));
    v.y = elu(fmaf(accLo.y, ia, bLo.y));
    v.z = elu(fmaf(accLo.z, ia, bLo.z));
    v.w = elu(fmaf(accLo.w, ia, bLo.w));
    *(float4*)&s_out[wip][lane * 4] = v;
    v.x = elu(fmaf(accHi.x, ib, bHi.x));
    v.y = elu(fmaf(accHi.y, ib, bHi.y));
    v.z = elu(fmaf(accHi.z, ib, bHi.z));
    v.w = elu(fmaf(accHi.w, ib, bHi.w));
    *(float4*)&s_out[wip][128 + lane * 4] = v;
    __syncthreads();

    // transposed writeback: thread t owns feature k=t, writes 8 node-values
    int nb0 = blockIdx.x * 8;
    int k = threadIdx.x;
    float vals[8];
#pragma unroll
    for (int n = 0; n < 8; n++) vals[n] = s_out[n][k];
    float4* dst = (float4*)(g_o1T + (size_t)k * OP + nb0);
    dst[0] = make_float4(vals[0], vals[1], vals[2], vals[3]);
    dst[1] = make_float4(vals[4], vals[5], vals[6], vals[7]);
}

// ---------------- launch 3: GEMM2 (cp.async double-buffered) + scores2 ------
// 128x128 tile/block. 256 threads: warp w (0..7) owns nodes 16w..16w+15,
// lane l owns cols 4l..4l+3.  B loads are lane-contiguous (conflict-free);
// A loads are warp-broadcast.  8x8-equivalent register tile (32 fma2/kk).
__global__ void __launch_bounds__(256, 2) k_gemm2s(const float* __restrict__ W2,
                                                   const float* __restrict__ a_src2,
                                                   const float* __restrict__ a_dst2) {
    __shared__ __align__(16) float sA[2][16][128];   // o1T chunk [kk][node]
    __shared__ __align__(16) float sB[2][16][128];   // W2 chunk  [kk][col]
    int tid = threadIdx.x;
    int l = tid & 31;                  // lane: cols 4l..4l+3
    int w = tid >> 5;                  // warp: nodes 16w..16w+15
    int n0 = blockIdx.x * 128;
    int nvalid = min(128, NN - n0);

    unsigned int sa_u = (unsigned int)__cvta_generic_to_shared(&sA[0][0][0]);
    unsigned int sb_u = (unsigned int)__cvta_generic_to_shared(&sB[0][0][0]);

    auto load_chunk = [&](int ck, int buf) {
#pragma unroll
        for (int r = 0; r < 2; r++) {
            int i = tid + 256 * r;                 // 0..511
            int kk = i >> 5, seg = i & 31;
            cp_async16(sa_u + (unsigned int)(buf * 2048 + kk * 128 + seg * 4) * 4,
                       g_o1T + (size_t)(ck * 16 + kk) * OP + n0 + seg * 4);
            cp_async16(sb_u + (unsigned int)(buf * 2048 + kk * 128 + seg * 4) * 4,
                       W2 + (size_t)(ck * 16 + kk) * 128 + seg * 4);
        }
        cp_commit();
    };

    ull acc[4][8];                      // [col][node-pair]
#pragma unroll
    for (int c = 0; c < 4; c++)
#pragma unroll
        for (int p = 0; p < 8; p++) acc[c][p] = 0ull;

    load_chunk(0, 0);
    for (int ck = 0; ck < 16; ck++) {
        cp_wait0();
        __syncthreads();
        if (ck < 15) load_chunk(ck + 1, (ck + 1) & 1);
        int buf = ck & 1;
#pragma unroll
        for (int kk = 0; kk < 16; kk++) {
            const ulonglong2* ap = (const ulonglong2*)&sA[buf][kk][16 * w];
            ulonglong2 a0 = ap[0];      // node pairs 0,1
            ulonglong2 a1 = ap[1];      // pairs 2,3
            ulonglong2 a2 = ap[2];      // pairs 4,5
            ulonglong2 a3 = ap[3];      // pairs 6,7
            float4 b = *(const float4*)&sB[buf][kk][4 * l];
            ull pb0 = pack2(b.x, b.x), pb1 = pack2(b.y, b.y);
            ull pb2 = pack2(b.z, b.z), pb3 = pack2(b.w, b.w);
            acc[0][0] = fma2(a0.x, pb0, acc[0][0]);
            acc[0][1] = fma2(a0.y, pb0, acc[0][1]);
            acc[0][2] = fma2(a1.x, pb0, acc[0][2]);
            acc[0][3] = fma2(a1.y, pb0, acc[0][3]);
            acc[0][4] = fma2(a2.x, pb0, acc[0][4]);
            acc[0][5] = fma2(a2.y, pb0, acc[0][5]);
            acc[0][6] = fma2(a3.x, pb0, acc[0][6]);
            acc[0][7] = fma2(a3.y, pb0, acc[0][7]);
            acc[1][0] = fma2(a0.x, pb1, acc[1][0]);
            acc[1][1] = fma2(a0.y, pb1, acc[1][1]);
            acc[1][2] = fma2(a1.x, pb1, acc[1][2]);
            acc[1][3] = fma2(a1.y, pb1, acc[1][3]);
            acc[1][4] = fma2(a2.x, pb1, acc[1][4]);
            acc[1][5] = fma2(a2.y, pb1, acc[1][5]);
            acc[1][6] = fma2(a3.x, pb1, acc[1][6]);
            acc[1][7] = fma2(a3.y, pb1, acc[1][7]);
            acc[2][0] = fma2(a0.x, pb2, acc[2][0]);
            acc[2][1] = fma2(a0.y, pb2, acc[2][1]);
            acc[2][2] = fma2(a1.x, pb2, acc[2][2]);
            acc[2][3] = fma2(a1.y, pb2, acc[2][3]);
            acc[2][4] = fma2(a2.x, pb2, acc[2][4]);
            acc[2][5] = fma2(a2.y, pb2, acc[2][5]);
            acc[2][6] = fma2(a3.x, pb2, acc[2][6]);
            acc[2][7] = fma2(a3.y, pb2, acc[2][7]);
            acc[3][0] = fma2(a0.x, pb3, acc[3][0]);
            acc[3][1] = fma2(a0.y, pb3, acc[3][1]);
            acc[3][2] = fma2(a1.x, pb3, acc[3][2]);
            acc[3][3] = fma2(a1.y, pb3, acc[3][3]);
            acc[3][4] = fma2(a2.x, pb3, acc[3][4]);
            acc[3][5] = fma2(a2.y, pb3, acc[3][5]);
            acc[3][6] = fma2(a3.x, pb3, acc[3][6]);
            acc[3][7] = fma2(a3.y, pb3, acc[3][7]);
        }
        __syncthreads();
    }

    // epilogue: per node-pair, write h2 + fused scores2
    int head = l >> 4;                  // lane 0-15 -> head 0, 16-31 -> head 1
    int coff = (4 * l) & 63;
    float4 as = *(const float4*)(a_src2 + head * 64 + coff);
    float4 ad = *(const float4*)(a_dst2 + head * 64 + coff);
#pragma unroll
    for (int p = 0; p < 8; p++) {
        float v0[4], v1[4];
#pragma unroll
        for (int c = 0; c < 4; c++) unpack2(acc[c][p], v0[c], v1[c]);
        int nl0 = 16 * w + 2 * p;
        float ps0 = v0[0] * as.x + v0[1] * as.y + v0[2] * as.z + v0[3] * as.w;
        float pd0 = v0[0] * ad.x + v0[1] * ad.y + v0[2] * ad.z + v0[3] * ad.w;
        float ps1 = v1[0] * as.x + v1[1] * as.y + v1[2] * as.z + v1[3] * as.w;
        float pd1 = v1[0] * ad.x + v1[1] * ad.y + v1[2] * ad.z + v1[3] * ad.w;
        if (nl0 < nvalid)
            *(float4*)(g_h2 + (size_t)(n0 + nl0) * 128 + 4 * l) =
                make_float4(v0[0], v0[1], v0[2], v0[3]);
        if (nl0 + 1 < nvalid)
            *(float4*)(g_h2 + (size_t)(n0 + nl0 + 1) * 128 + 4 * l) =
                make_float4(v1[0], v1[1], v1[2], v1[3]);
#pragma unroll
        for (int o = 8; o; o >>= 1) {   // reduce within 16-lane halves
            ps0 += __shfl_down_sync(0xFFFFFFFFu, ps0, o);
            pd0 += __shfl_down_sync(0xFFFFFFFFu, pd0, o);
            ps1 += __shfl_down_sync(0xFFFFFFFFu, ps1, o);
            pd1 += __shfl_down_sync(0xFFFFFFFFu, pd1, o);
        }
        if ((l & 15) == 0) {            // lane 0 (head 0), lane 16 (head 1)
            if (nl0 < nvalid) {
                g_ssrc2[(n0 + nl0) * 2 + head] = ps0;
                g_sdst2[(n0 + nl0) * 2 + head] = pd0;
            }
            if (nl0 + 1 < nvalid) {
                g_ssrc2[(n0 + nl0 + 1) * 2 + head] = ps1;
                g_sdst2[(n0 + nl0 + 1) * 2 + head] = pd1;
            }
        }
    }
}

// ---------------- launch 4: layer-2 aggregation + FC + sigmoid --------------
__global__ void __launch_bounds__(256) k_agg2(const float* __restrict__ b2,
                                              const float* __restrict__ Wfc,
                                              const float* __restrict__ bfc,
                                              float* __restrict__ out) {
    __shared__ __align__(8) float2 s_w2[8][32];
    __shared__ int s_si[8][32];
    int t0 = blockIdx.x * blockDim.x + threadIdx.x;
    if (t0 < NN) g_deg[t0] = 0;
    if (t0 < NBLK) g_pub[t0] = 0;
    if (t0 == 0) g_bar = 0;

    int wid = t0 >> 5;
    if (wid >= NN) return;
    int wip = threadIdx.x >> 5;
    int lane = threadIdx.x & 31;
    int rs = g_rs[wid], re = g_rs[wid + 1];
    float2 sd = *(const float2*)(g_sdst2 + wid * 2);

    float2 mx = make_float2(-3.4e38f, -3.4e38f);
    for (int j = rs + lane; j < re; j += 32) {
        int s = g_csr[j];
        float2 ss = *(const float2*)(g_ssrc2 + s * 2);
        mx.x = fmaxf(mx.x, lrelu(ss.x + sd.x));
        mx.y = fmaxf(mx.y, lrelu(ss.y + sd.y));
    }
#pragma unroll
    for (int o = 16; o; o >>= 1) {
        mx.x = fmaxf(mx.x, __shfl_xor_sync(0xFFFFFFFFu, mx.x, o));
        mx.y = fmaxf(mx.y, __shfl_xor_sync(0xFFFFFFFFu, mx.y, o));
    }

    float2 zv = make_float2(0.f, 0.f);
    ull a0 = 0, a1 = 0;
    for (int base = rs; base < re; base += 32) {
        int cnt = min(32, re - base);
        int s_l = 0;
        float2 wv = make_float2(0.f, 0.f);
        if (lane < cnt) {
            s_l = g_csr[base + lane];
            float2 ss = *(const float2*)(g_ssrc2 + s_l * 2);
            wv.x = __expf(lrelu(ss.x + sd.x) - mx.x);
            wv.y = __expf(lrelu(ss.y + sd.y) - mx.y);
            zv.x += wv.x; zv.y += wv.y;
        }
        __syncwarp();
        s_w2[wip][lane] = wv;
        s_si[wip][lane] = s_l;
        __syncwarp();
        int t = 0;
        for (; t + 2 <= cnt; t += 2) {
            float2 w20 = s_w2[wip][t];
            float2 w21 = s_w2[wip][t + 1];
            int s0 = s_si[wip][t];
            int s1 = s_si[wip][t + 1];
            const ulonglong2* hp0 = (const ulonglong2*)(g_h2 + (size_t)s0 * 128);
            const ulonglong2* hp1 = (const ulonglong2*)(g_h2 + (size_t)s1 * 128);
            ulonglong2 h0 = hp0[lane];
            ulonglong2 h1 = hp1[lane];
            float wa0 = (lane < 16) ? w20.x : w20.y;
            float wa1 = (lane < 16) ? w21.x : w21.y;
            ull wp0 = pack2(wa0, wa0);
            ull wp1 = pack2(wa1, wa1);
            a0 = fma2(h0.x, wp0, a0); a1 = fma2(h0.y, wp0, a1);
            a0 = fma2(h1.x, wp1, a0); a1 = fma2(h1.y, wp1, a1);
        }
        if (t < cnt) {
            float2 w20 = s_w2[wip][t];
            int s0 = s_si[wip][t];
            const ulonglong2* hp0 = (const ulonglong2*)(g_h2 + (size_t)s0 * 128);
            ulonglong2 h0 = hp0[lane];
            float wa0 = (lane < 16) ? w20.x : w20.y;
            ull wp0 = pack2(wa0, wa0);
            a0 = fma2(h0.x, wp0, a0); a1 = fma2(h0.y, wp0, a1);
        }
    }
#pragma unroll
    for (int o = 16; o; o >>= 1) {
        zv.x += __shfl_xor_sync(0xFFFFFFFFu, zv.x, o);
        zv.y += __shfl_xor_sync(0xFFFFFFFFu, zv.y, o);
    }
    float iz = __fdividef(1.f, ((lane < 16) ? zv.x : zv.y) + EPS);
    float4 acc;
    unpack2(a0, acc.x, acc.y); unpack2(a1, acc.z, acc.w);
    float4 b = *(const float4*)(b2 + lane * 4);
    float4 wf = *(const float4*)(Wfc + lane * 4);
    float t = elu(fmaf(acc.x, iz, b.x)) * wf.x
            + elu(fmaf(acc.y, iz, b.y)) * wf.y
            + elu(fmaf(acc.z, iz, b.z)) * wf.z
            + elu(fmaf(acc.w, iz, b.w)) * wf.w;
#pragma unroll
    for (int o = 16; o; o >>= 1) t += __shfl_down_sync(0xFFFFFFFFu, t, o);
    if (lane == 0) {
        float s = t + bfc[0];
        out[wid] = __fdividef(1.f, 1.f + __expf(-s));
    }
}

// ---------------- launch ----------------
extern "C" void kernel_launch(void* const* d_in, const int* in_sizes, int n_in,
                              void* d_out, int out_size) {
    const float* x      = (const float*)d_in[0];
    const void*  ei     = d_in[1];
    const float* W1     = (const float*)d_in[2];
    const float* a_src1 = (const float*)d_in[3];
    const float* a_dst1 = (const float*)d_in[4];
    const float* b1     = (const float*)d_in[5];
    const float* W2     = (const float*)d_in[6];
    const float* a_src2 = (const float*)d_in[7];
    const float* a_dst2 = (const float*)d_in[8];
    const float* b2     = (const float*)d_in[9];
    const float* Wfc    = (const float*)d_in[10];
    const float* bfc    = (const float*)d_in[11];
    float* out = (float*)d_out;

    k_conv_gemm1s<<<NCONV + NN / 16, 256>>>(ei, x, W1, a_src1, a_dst1); // 0
    k_scan_scatter<<<NBLK, SCAN_B>>>();                                // 1
    k_agg1<<<(NN + 7) / 8, 256>>>(b1);                                 // 2
    k_gemm2s<<<NGB2, 256>>>(W2, a_src2, a_dst2);                       // 3 <- ncu
    k_agg2<<<(NN + 7) / 8, 256>>>(b2, Wfc, bfc, out);                  // 4
}

// round 15
// speedup vs baseline: 1.0739x; 1.0281x over previous
#include <cuda_runtime.h>
#include <cuda_bf16.h>
#include <cstdint>

#define NN 50000
#define EE 300000
#define ETOT (EE + NN)          // edges + self loops
#define NEG_SLOPE 0.2f
#define EPS 1e-16f
#define SCAN_B 512
#define NBLK ((NN + SCAN_B - 1) / SCAN_B)   // 98 (co-resident on 148 SMs)
#define NCONV ((ETOT + 255) / 256)          // 1368 convert blocks
#define NGB2 ((NN + 127) / 128)             // 391 gemm2 blocks
#define OP 50048                            // padded node count (6256 blocks of 8)

typedef unsigned long long ull;

// ---------------- scratch (static device allocations only) ----------------
// INVARIANT: g_deg, g_pub, g_bar are zero at every kernel_launch entry.
__device__ int g_srcR[ETOT];
__device__ int g_dstR[ETOT];
__device__ int g_rank[ETOT];
__device__ int g_csr[ETOT];
__device__ int g_deg[NN];
__device__ int g_rs[NN + 1];
__device__ int g_pub[NBLK];
__device__ int g_bar;

__device__ float g_h1[NN * 256];
__device__ float g_ssrc1[NN * 4];
__device__ float g_sdst1[NN * 4];
// layer-1 ELU output, node-block-tiled: [node/8][k][8]  (256*8 = 2048 floats/block)
// node-blocks >= 6250 stay 0 (zero-init, never written)
__device__ float g_o1T[(OP / 8) * 256 * 8];

__device__ float g_h2[NN * 128];
__device__ float g_ssrc2[NN * 2];
__device__ float g_sdst2[NN * 2];

// ---------------- helpers ----------------
__device__ __forceinline__ float lrelu(float x) {
    return x > 0.f ? x : NEG_SLOPE * x;
}
__device__ __forceinline__ float elu(float x) {
    return x > 0.f ? x : expm1f(x);
}
__device__ __forceinline__ ull pack2(float a, float b) {
    ull r; asm("mov.b64 %0,{%1,%2};" : "=l"(r) : "f"(a), "f"(b)); return r;
}
__device__ __forceinline__ void unpack2(ull p, float& a, float& b) {
    asm("mov.b64 {%0,%1},%2;" : "=f"(a), "=f"(b) : "l"(p));
}
__device__ __forceinline__ ull fma2(ull a, ull b, ull c) {
    ull d; asm("fma.rn.f32x2 %0,%1,%2,%3;" : "=l"(d) : "l"(a), "l"(b), "l"(c));
    return d;
}
__device__ __forceinline__ void cp_async16(unsigned int smem, const void* g) {
    asm volatile("cp.async.cg.shared.global [%0],[%1],16;" :: "r"(smem), "l"(g));
}
__device__ __forceinline__ void cp_commit() {
    asm volatile("cp.async.commit_group;");
}
__device__ __forceinline__ void cp_wait0() {
    asm volatile("cp.async.wait_group 0;" ::: "memory");
}

// ============ launch 0: edge convert + GEMM1+scores1 ========================
__global__ void __launch_bounds__(256) k_conv_gemm1s(
        const void* __restrict__ ei,
        const float* __restrict__ x, const float* __restrict__ W1,
        const float* __restrict__ a_src1, const float* __restrict__ a_dst1) {
    __shared__ __align__(16) float sxt[27 * 16];
    __shared__ __align__(16) float sh1[16 * 256];
    int tid = threadIdx.x;

    if (blockIdx.x < NCONV) {
        const int* ei32 = (const int*)ei;
        int probe = ei32[2 * tid + 1];
        int any = __syncthreads_or(probe);
        int is64 = (any == 0);
        int e = blockIdx.x * 256 + tid;
        if (e >= ETOT) return;
        int s, d;
        if (e >= EE) {
            s = d = e - EE;
        } else if (is64) {
            const long long* p = (const long long*)ei;
            s = (int)p[e]; d = (int)p[EE + e];
        } else {
            const int* p = (const int*)ei;
            s = p[e]; d = p[EE + e];
        }
        g_srcR[e] = s; g_dstR[e] = d;
        g_rank[e] = atomicAdd(&g_deg[d], 1);
        return;
    }

    int n0 = (blockIdx.x - NCONV) * 16;
    for (int i = tid; i < 27 * 16; i += 256) {
        int k = i >> 4, m = i & 15;
        sxt[i] = x[(n0 + m) * 27 + k];
    }
    float w[27];
#pragma unroll
    for (int k = 0; k < 27; k++) w[k] = W1[k * 256 + tid];
    __syncthreads();
    ull acc[8];
#pragma unroll
    for (int p = 0; p < 8; p++) acc[p] = 0ull;
#pragma unroll
    for (int k = 0; k < 27; k++) {
        ull wp = pack2(w[k], w[k]);
        const ulonglong2* xp = (const ulonglong2*)(sxt + k * 16);
#pragma unroll
        for (int q = 0; q < 4; q++) {
            ulonglong2 xv = xp[q];
            acc[2 * q]     = fma2(xv.x, wp, acc[2 * q]);
            acc[2 * q + 1] = fma2(xv.y, wp, acc[2 * q + 1]);
        }
    }
#pragma unroll
    for (int p = 0; p < 8; p++) {
        float lo, hi; unpack2(acc[p], lo, hi);
        g_h1[(size_t)(n0 + 2 * p) * 256 + tid] = lo;
        g_h1[(size_t)(n0 + 2 * p + 1) * 256 + tid] = hi;
        sh1[(2 * p) * 256 + tid] = lo;
        sh1[(2 * p + 1) * 256 + tid] = hi;
    }
    __syncthreads();

    int wrp = tid >> 5, lane = tid & 31;
    const float4* aS = (const float4*)a_src1;
    const float4* aD = (const float4*)a_dst1;
    float4 sA = aS[lane], sB = aS[32 + lane];
    float4 dA = aD[lane], dB = aD[32 + lane];
#pragma unroll
    for (int mi = 0; mi < 2; mi++) {
        int m = wrp * 2 + mi;
        const float4* hr = (const float4*)(sh1 + m * 256);
        float4 hA = hr[lane];
        float4 hB = hr[32 + lane];
        float psA = hA.x * sA.x + hA.y * sA.y + hA.z * sA.z + hA.w * sA.w;
        float pdA = hA.x * dA.x + hA.y * dA.y + hA.z * dA.z + hA.w * dA.w;
        float psB = hB.x * sB.x + hB.y * sB.y + hB.z * sB.z + hB.w * sB.w;
        float pdB = hB.x * dB.x + hB.y * dB.y + hB.z * dB.z + hB.w * dB.w;
#pragma unroll
        for (int o = 8; o; o >>= 1) {
            psA += __shfl_down_sync(0xFFFFFFFFu, psA, o);
            pdA += __shfl_down_sync(0xFFFFFFFFu, pdA, o);
            psB += __shfl_down_sync(0xFFFFFFFFu, psB, o);
            pdB += __shfl_down_sync(0xFFFFFFFFu, pdB, o);
        }
        int n = n0 + m;
        if (lane == 0) {
            g_ssrc1[n * 4 + 0] = psA; g_sdst1[n * 4 + 0] = pdA;
            g_ssrc1[n * 4 + 2] = psB; g_sdst1[n * 4 + 2] = pdB;
        }
        if (lane == 16) {
            g_ssrc1[n * 4 + 1] = psA; g_sdst1[n * 4 + 1] = pdA;
            g_ssrc1[n * 4 + 3] = psB; g_sdst1[n * 4 + 3] = pdB;
        }
    }
}

// ---------------- launch 1: scan (lookback) + grid barrier + scatter --------
__global__ void __launch_bounds__(SCAN_B) k_scan_scatter() {
    __shared__ int sh[SCAN_B];
    __shared__ int s_sum;
    int b = blockIdx.x, t = threadIdx.x;
    int i = b * SCAN_B + t;
    int v = (i < NN) ? g_deg[i] : 0;
    sh[t] = v;
    __syncthreads();
#pragma unroll
    for (int d = 1; d < SCAN_B; d <<= 1) {
        int u = (t >= d) ? sh[t - d] : 0;
        __syncthreads();
        sh[t] += u;
        __syncthreads();
    }
    int excl = sh[t] - v;
    int agg = sh[SCAN_B - 1];
    if (t == 0) {
        s_sum = 0;
        atomicExch(&g_pub[b], agg + 1);
    }
    __syncthreads();
    if (t < b) {
        int p;
        do { p = *(volatile int*)&g_pub[t]; } while (p == 0);
        atomicAdd(&s_sum, p - 1);
    }
    __syncthreads();
    if (i < NN) g_rs[i] = excl + s_sum;
    if (b == NBLK - 1 && t == SCAN_B - 1) g_rs[NN] = ETOT;

    __threadfence();
    __syncthreads();
    if (t == 0) {
        atomicAdd(&g_bar, 1);
        while (*(volatile int*)&g_bar < NBLK) {}
    }
    __syncthreads();
    __threadfence();

    for (int e = b * SCAN_B + t; e < ETOT; e += NBLK * SCAN_B) {
        int d = g_dstR[e];
        g_csr[g_rs[d] + g_rank[e]] = g_srcR[e];
    }
}

// ---------------- launch 2: layer-1 aggregation, warp / dst ----------------
// epilogue writes node-block-tiled o1T [node/8][k][8] via smem staging —
// thread k stores 32 B at block*2048 + k*8: fully coalesced (1 KB / warp).
__global__ void __launch_bounds__(256) k_agg1(const float* __restrict__ b1) {
    __shared__ __align__(16) float4 s_w4[8][32];
    __shared__ int s_si[8][32];
    __shared__ __align__(16) float s_out[8][256];   // staging for transpose
    int wid = (blockIdx.x * blockDim.x + threadIdx.x) >> 5;
    int wip = threadIdx.x >> 5;
    int lane = threadIdx.x & 31;
    int rs = g_rs[wid], re = g_rs[wid + 1];
    float4 sd = *(const float4*)(g_sdst1 + wid * 4);

    float4 mx = make_float4(-3.4e38f, -3.4e38f, -3.4e38f, -3.4e38f);
    for (int j = rs + lane; j < re; j += 32) {
        int s = g_csr[j];
        float4 ss = *(const float4*)(g_ssrc1 + s * 4);
        mx.x = fmaxf(mx.x, lrelu(ss.x + sd.x));
        mx.y = fmaxf(mx.y, lrelu(ss.y + sd.y));
        mx.z = fmaxf(mx.z, lrelu(ss.z + sd.z));
        mx.w = fmaxf(mx.w, lrelu(ss.w + sd.w));
    }
#pragma unroll
    for (int o = 16; o; o >>= 1) {
        mx.x = fmaxf(mx.x, __shfl_xor_sync(0xFFFFFFFFu, mx.x, o));
        mx.y = fmaxf(mx.y, __shfl_xor_sync(0xFFFFFFFFu, mx.y, o));
        mx.z = fmaxf(mx.z, __shfl_xor_sync(0xFFFFFFFFu, mx.z, o));
        mx.w = fmaxf(mx.w, __shfl_xor_sync(0xFFFFFFFFu, mx.w, o));
    }

    float4 zv = make_float4(0.f, 0.f, 0.f, 0.f);
    ull aL0 = 0, aL1 = 0, aH0 = 0, aH1 = 0;
    for (int base = rs; base < re; base += 32) {
        int cnt = min(32, re - base);
        int s_l = 0;
        float4 wv = make_float4(0.f, 0.f, 0.f, 0.f);
        if (lane < cnt) {
            s_l = g_csr[base + lane];
            float4 ss = *(const float4*)(g_ssrc1 + s_l * 4);
            wv.x = __expf(lrelu(ss.x + sd.x) - mx.x);
            wv.y = __expf(lrelu(ss.y + sd.y) - mx.y);
            wv.z = __expf(lrelu(ss.z + sd.z) - mx.z);
            wv.w = __expf(lrelu(ss.w + sd.w) - mx.w);
            zv.x += wv.x; zv.y += wv.y; zv.z += wv.z; zv.w += wv.w;
        }
        __syncwarp();
        s_w4[wip][lane] = wv;
        s_si[wip][lane] = s_l;
        __syncwarp();
        int t = 0;
        for (; t + 2 <= cnt; t += 2) {
            float4 w40 = s_w4[wip][t];
            float4 w41 = s_w4[wip][t + 1];
            int s0 = s_si[wip][t];
            int s1 = s_si[wip][t + 1];
            const ulonglong2* hp0 = (const ulonglong2*)(g_h1 + (size_t)s0 * 256);
            const ulonglong2* hp1 = (const ulonglong2*)(g_h1 + (size_t)s1 * 256);
            ulonglong2 l0 = hp0[lane], h0 = hp0[32 + lane];
            ulonglong2 l1 = hp1[lane], h1 = hp1[32 + lane];
            ull wa0 = pack2((lane < 16) ? w40.x : w40.y, (lane < 16) ? w40.x : w40.y);
            ull wb0 = pack2((lane < 16) ? w40.z : w40.w, (lane < 16) ? w40.z : w40.w);
            ull wa1 = pack2((lane < 16) ? w41.x : w41.y, (lane < 16) ? w41.x : w41.y);
            ull wb1 = pack2((lane < 16) ? w41.z : w41.w, (lane < 16) ? w41.z : w41.w);
            aL0 = fma2(l0.x, wa0, aL0); aL1 = fma2(l0.y, wa0, aL1);
            aH0 = fma2(h0.x, wb0, aH0); aH1 = fma2(h0.y, wb0, aH1);
            aL0 = fma2(l1.x, wa1, aL0); aL1 = fma2(l1.y, wa1, aL1);
            aH0 = fma2(h1.x, wb1, aH0); aH1 = fma2(h1.y, wb1, aH1);
        }
        if (t < cnt) {
            float4 w40 = s_w4[wip][t];
            int s0 = s_si[wip][t];
            const ulonglong2* hp0 = (const ulonglong2*)(g_h1 + (size_t)s0 * 256);
            ulonglong2 l0 = hp0[lane], h0 = hp0[32 + lane];
            ull wa0 = pack2((lane < 16) ? w40.x : w40.y, (lane < 16) ? w40.x : w40.y);
            ull wb0 = pack2((lane < 16) ? w40.z : w40.w, (lane < 16) ? w40.z : w40.w);
            aL0 = fma2(l0.x, wa0, aL0); aL1 = fma2(l0.y, wa0, aL1);
            aH0 = fma2(h0.x, wb0, aH0); aH1 = fma2(h0.y, wb0, aH1);
        }
    }
#pragma unroll
    for (int o = 16; o; o >>= 1) {
        zv.x += __shfl_xor_sync(0xFFFFFFFFu, zv.x, o);
        zv.y += __shfl_xor_sync(0xFFFFFFFFu, zv.y, o);
        zv.z += __shfl_xor_sync(0xFFFFFFFFu, zv.z, o);
        zv.w += __shfl_xor_sync(0xFFFFFFFFu, zv.w, o);
    }
    float ia = __fdividef(1.f, ((lane < 16) ? zv.x : zv.y) + EPS);
    float ib = __fdividef(1.f, ((lane < 16) ? zv.z : zv.w) + EPS);
    float4 accLo, accHi;
    unpack2(aL0, accLo.x, accLo.y); unpack2(aL1, accLo.z, accLo.w);
    unpack2(aH0, accHi.x, accHi.y); unpack2(aH1, accHi.z, accHi.w);
    float4 bLo = *(const float4*)(b1 + lane * 4);
    float4 bHi = *(const float4*)(b1 + 128 + lane * 4);
    float4 v;
    v.x = elu(fmaf(accLo.x, ia, bLo.x));
    v.y = elu(fmaf(accLo.y, ia, bLo.y));
    v.z = elu(fmaf(accLo.z, ia, bLo.z));
    v.w = elu(fmaf(accLo.w, ia, bLo.w));
    *(float4*)&s_out[wip][lane * 4] = v;
    v.x = elu(fmaf(accHi.x, ib, bHi.x));
    v.y = elu(fmaf(accHi.y, ib, bHi.y));
    v.z = elu(fmaf(accHi.z, ib, bHi.z));
    v.w = elu(fmaf(accHi.w, ib, bHi.w));
    *(float4*)&s_out[wip][128 + lane * 4] = v;
    __syncthreads();

    // tiled writeback: thread k writes its 8 node-values CONTIGUOUSLY
    int k = threadIdx.x;
    float vals[8];
#pragma unroll
    for (int n = 0; n < 8; n++) vals[n] = s_out[n][k];
    float4* dst = (float4*)(g_o1T + (size_t)blockIdx.x * 2048 + k * 8);
    dst[0] = make_float4(vals[0], vals[1], vals[2], vals[3]);
    dst[1] = make_float4(vals[4], vals[5], vals[6], vals[7]);
}

// ---------------- launch 3: GEMM2 (cp.async double-buffered) + scores2 ------
// 128x128 tile/block. warp w owns nodes 16w..16w+15, lane l owns cols 4l..4l+3.
// B loads lane-contiguous (conflict-free); A loads warp-broadcast.
__global__ void __launch_bounds__(256, 2) k_gemm2s(const float* __restrict__ W2,
                                                   const float* __restrict__ a_src2,
                                                   const float* __restrict__ a_dst2) {
    __shared__ __align__(16) float sA[2][16][128];   // o1T chunk [kk][node]
    __shared__ __align__(16) float sB[2][16][128];   // W2 chunk  [kk][col]
    int tid = threadIdx.x;
    int l = tid & 31;                  // lane: cols 4l..4l+3
    int w = tid >> 5;                  // warp: nodes 16w..16w+15
    int n0 = blockIdx.x * 128;
    int nvalid = min(128, NN - n0);
    int nb0 = blockIdx.x * 16;         // first node-block of this tile

    unsigned int sa_u = (unsigned int)__cvta_generic_to_shared(&sA[0][0][0]);
    unsigned int sb_u = (unsigned int)__cvta_generic_to_shared(&sB[0][0][0]);

    auto load_chunk = [&](int ck, int buf) {
#pragma unroll
        for (int r = 0; r < 2; r++) {
            int i = tid + 256 * r;                 // 0..511
            int kk = i >> 5, seg = i & 31;         // seg: 4-node group
            // o1T tiled: [nb][k][8]; seg covers nodes seg*4..seg*4+3
            const float* srcA = g_o1T
                + (size_t)(nb0 + (seg >> 1)) * 2048
                + (ck * 16 + kk) * 8 + (seg & 1) * 4;
            cp_async16(sa_u + (unsigned int)(buf * 2048 + kk * 128 + seg * 4) * 4,
                       srcA);
            cp_async16(sb_u + (unsigned int)(buf * 2048 + kk * 128 + seg * 4) * 4,
                       W2 + (size_t)(ck * 16 + kk) * 128 + seg * 4);
        }
        cp_commit();
    };

    ull acc[4][8];                      // [col][node-pair]
#pragma unroll
    for (int c = 0; c < 4; c++)
#pragma unroll
        for (int p = 0; p < 8; p++) acc[c][p] = 0ull;

    load_chunk(0, 0);
    for (int ck = 0; ck < 16; ck++) {
        cp_wait0();
        __syncthreads();
        if (ck < 15) load_chunk(ck + 1, (ck + 1) & 1);
        int buf = ck & 1;
#pragma unroll
        for (int kk = 0; kk < 16; kk++) {
            const ulonglong2* ap = (const ulonglong2*)&sA[buf][kk][16 * w];
            ulonglong2 a0 = ap[0];
            ulonglong2 a1 = ap[1];
            ulonglong2 a2 = ap[2];
            ulonglong2 a3 = ap[3];
            float4 b = *(const float4*)&sB[buf][kk][4 * l];
            ull pb0 = pack2(b.x, b.x), pb1 = pack2(b.y, b.y);
            ull pb2 = pack2(b.z, b.z), pb3 = pack2(b.w, b.w);
            acc[0][0] = fma2(a0.x, pb0, acc[0][0]);
            acc[0][1] = fma2(a0.y, pb0, acc[0][1]);
            acc[0][2] = fma2(a1.x, pb0, acc[0][2]);
            acc[0][3] = fma2(a1.y, pb0, acc[0][3]);
            acc[0][4] = fma2(a2.x, pb0, acc[0][4]);
            acc[0][5] = fma2(a2.y, pb0, acc[0][5]);
            acc[0][6] = fma2(a3.x, pb0, acc[0][6]);
            acc[0][7] = fma2(a3.y, pb0, acc[0][7]);
            acc[1][0] = fma2(a0.x, pb1, acc[1][0]);
            acc[1][1] = fma2(a0.y, pb1, acc[1][1]);
            acc[1][2] = fma2(a1.x, pb1, acc[1][2]);
            acc[1][3] = fma2(a1.y, pb1, acc[1][3]);
            acc[1][4] = fma2(a2.x, pb1, acc[1][4]);
            acc[1][5] = fma2(a2.y, pb1, acc[1][5]);
            acc[1][6] = fma2(a3.x, pb1, acc[1][6]);
            acc[1][7] = fma2(a3.y, pb1, acc[1][7]);
            acc[2][0] = fma2(a0.x, pb2, acc[2][0]);
            acc[2][1] = fma2(a0.y, pb2, acc[2][1]);
            acc[2][2] = fma2(a1.x, pb2, acc[2][2]);
            acc[2][3] = fma2(a1.y, pb2, acc[2][3]);
            acc[2][4] = fma2(a2.x, pb2, acc[2][4]);
            acc[2][5] = fma2(a2.y, pb2, acc[2][5]);
            acc[2][6] = fma2(a3.x, pb2, acc[2][6]);
            acc[2][7] = fma2(a3.y, pb2, acc[2][7]);
            acc[3][0] = fma2(a0.x, pb3, acc[3][0]);
            acc[3][1] = fma2(a0.y, pb3, acc[3][1]);
            acc[3][2] = fma2(a1.x, pb3, acc[3][2]);
            acc[3][3] = fma2(a1.y, pb3, acc[3][3]);
            acc[3][4] = fma2(a2.x, pb3, acc[3][4]);
            acc[3][5] = fma2(a2.y, pb3, acc[3][5]);
            acc[3][6] = fma2(a3.x, pb3, acc[3][6]);
            acc[3][7] = fma2(a3.y, pb3, acc[3][7]);
        }
        __syncthreads();
    }

    // epilogue: per node-pair, write h2 + fused scores2
    int head = l >> 4;
    int coff = (4 * l) & 63;
    float4 as = *(const float4*)(a_src2 + head * 64 + coff);
    float4 ad = *(const float4*)(a_dst2 + head * 64 + coff);
#pragma unroll
    for (int p = 0; p < 8; p++) {
        float v0[4], v1[4];
#pragma unroll
        for (int c = 0; c < 4; c++) unpack2(acc[c][p], v0[c], v1[c]);
        int nl0 = 16 * w + 2 * p;
        float ps0 = v0[0] * as.x + v0[1] * as.y + v0[2] * as.z + v0[3] * as.w;
        float pd0 = v0[0] * ad.x + v0[1] * ad.y + v0[2] * ad.z + v0[3] * ad.w;
        float ps1 = v1[0] * as.x + v1[1] * as.y + v1[2] * as.z + v1[3] * as.w;
        float pd1 = v1[0] * ad.x + v1[1] * ad.y + v1[2] * ad.z + v1[3] * ad.w;
        if (nl0 < nvalid)
            *(float4*)(g_h2 + (size_t)(n0 + nl0) * 128 + 4 * l) =
                make_float4(v0[0], v0[1], v0[2], v0[3]);
        if (nl0 + 1 < nvalid)
            *(float4*)(g_h2 + (size_t)(n0 + nl0 + 1) * 128 + 4 * l) =
                make_float4(v1[0], v1[1], v1[2], v1[3]);
#pragma unroll
        for (int o = 8; o; o >>= 1) {
            ps0 += __shfl_down_sync(0xFFFFFFFFu, ps0, o);
            pd0 += __shfl_down_sync(0xFFFFFFFFu, pd0, o);
            ps1 += __shfl_down_sync(0xFFFFFFFFu, ps1, o);
            pd1 += __shfl_down_sync(0xFFFFFFFFu, pd1, o);
        }
        if ((l & 15) == 0) {
            if (nl0 < nvalid) {
                g_ssrc2[(n0 + nl0) * 2 + head] = ps0;
                g_sdst2[(n0 + nl0) * 2 + head] = pd0;
            }
            if (nl0 + 1 < nvalid) {
                g_ssrc2[(n0 + nl0 + 1) * 2 + head] = ps1;
                g_sdst2[(n0 + nl0 + 1) * 2 + head] = pd1;
            }
        }
    }
}

// ---------------- launch 4: layer-2 aggregation + FC + sigmoid --------------
__global__ void __launch_bounds__(256) k_agg2(const float* __restrict__ b2,
                                              const float* __restrict__ Wfc,
                                              const float* __restrict__ bfc,
                                              float* __restrict__ out) {
    __shared__ __align__(8) float2 s_w2[8][32];
    __shared__ int s_si[8][32];
    int t0 = blockIdx.x * blockDim.x + threadIdx.x;
    if (t0 < NN) g_deg[t0] = 0;
    if (t0 < NBLK) g_pub[t0] = 0;
    if (t0 == 0) g_bar = 0;

    int wid = t0 >> 5;
    if (wid >= NN) return;
    int wip = threadIdx.x >> 5;
    int lane = threadIdx.x & 31;
    int rs = g_rs[wid], re = g_rs[wid + 1];
    float2 sd = *(const float2*)(g_sdst2 + wid * 2);

    float2 mx = make_float2(-3.4e38f, -3.4e38f);
    for (int j = rs + lane; j < re; j += 32) {
        int s = g_csr[j];
        float2 ss = *(const float2*)(g_ssrc2 + s * 2);
        mx.x = fmaxf(mx.x, lrelu(ss.x + sd.x));
        mx.y = fmaxf(mx.y, lrelu(ss.y + sd.y));
    }
#pragma unroll
    for (int o = 16; o; o >>= 1) {
        mx.x = fmaxf(mx.x, __shfl_xor_sync(0xFFFFFFFFu, mx.x, o));
        mx.y = fmaxf(mx.y, __shfl_xor_sync(0xFFFFFFFFu, mx.y, o));
    }

    float2 zv = make_float2(0.f, 0.f);
    ull a0 = 0, a1 = 0;
    for (int base = rs; base < re; base += 32) {
        int cnt = min(32, re - base);
        int s_l = 0;
        float2 wv = make_float2(0.f, 0.f);
        if (lane < cnt) {
            s_l = g_csr[base + lane];
            float2 ss = *(const float2*)(g_ssrc2 + s_l * 2);
            wv.x = __expf(lrelu(ss.x + sd.x) - mx.x);
            wv.y = __expf(lrelu(ss.y + sd.y) - mx.y);
            zv.x += wv.x; zv.y += wv.y;
        }
        __syncwarp();
        s_w2[wip][lane] = wv;
        s_si[wip][lane] = s_l;
        __syncwarp();
        int t = 0;
        for (; t + 2 <= cnt; t += 2) {
            float2 w20 = s_w2[wip][t];
            float2 w21 = s_w2[wip][t + 1];
            int s0 = s_si[wip][t];
            int s1 = s_si[wip][t + 1];
            const ulonglong2* hp0 = (const ulonglong2*)(g_h2 + (size_t)s0 * 128);
            const ulonglong2* hp1 = (const ulonglong2*)(g_h2 + (size_t)s1 * 128);
            ulonglong2 h0 = hp0[lane];
            ulonglong2 h1 = hp1[lane];
            float wa0 = (lane < 16) ? w20.x : w20.y;
            float wa1 = (lane < 16) ? w21.x : w21.y;
            ull wp0 = pack2(wa0, wa0);
            ull wp1 = pack2(wa1, wa1);
            a0 = fma2(h0.x, wp0, a0); a1 = fma2(h0.y, wp0, a1);
            a0 = fma2(h1.x, wp1, a0); a1 = fma2(h1.y, wp1, a1);
        }
        if (t < cnt) {
            float2 w20 = s_w2[wip][t];
            int s0 = s_si[wip][t];
            const ulonglong2* hp0 = (const ulonglong2*)(g_h2 + (size_t)s0 * 128);
            ulonglong2 h0 = hp0[lane];
            float wa0 = (lane < 16) ? w20.x : w20.y;
            ull wp0 = pack2(wa0, wa0);
            a0 = fma2(h0.x, wp0, a0); a1 = fma2(h0.y, wp0, a1);
        }
    }
#pragma unroll
    for (int o = 16; o; o >>= 1) {
        zv.x += __shfl_xor_sync(0xFFFFFFFFu, zv.x, o);
        zv.y += __shfl_xor_sync(0xFFFFFFFFu, zv.y, o);
    }
    float iz = __fdividef(1.f, ((lane < 16) ? zv.x : zv.y) + EPS);
    float4 acc;
    unpack2(a0, acc.x, acc.y); unpack2(a1, acc.z, acc.w);
    float4 b = *(const float4*)(b2 + lane * 4);
    float4 wf = *(const float4*)(Wfc + lane * 4);
    float t = elu(fmaf(acc.x, iz, b.x)) * wf.x
            + elu(fmaf(acc.y, iz, b.y)) * wf.y
            + elu(fmaf(acc.z, iz, b.z)) * wf.z
            + elu(fmaf(acc.w, iz, b.w)) * wf.w;
#pragma unroll
    for (int o = 16; o; o >>= 1) t += __shfl_down_sync(0xFFFFFFFFu, t, o);
    if (lane == 0) {
        float s = t + bfc[0];
        out[wid] = __fdividef(1.f, 1.f + __expf(-s));
    }
}

// ---------------- launch ----------------
extern "C" void kernel_launch(void* const* d_in, const int* in_sizes, int n_in,
                              void* d_out, int out_size) {
    const float* x      = (const float*)d_in[0];
    const void*  ei     = d_in[1];
    const float* W1     = (const float*)d_in[2];
    const float* a_src1 = (const float*)d_in[3];
    const float* a_dst1 = (const float*)d_in[4];
    const float* b1     = (const float*)d_in[5];
    const float* W2     = (const float*)d_in[6];
    const float* a_src2 = (const float*)d_in[7];
    const float* a_dst2 = (const float*)d_in[8];
    const float* b2     = (const float*)d_in[9];
    const float* Wfc    = (const float*)d_in[10];
    const float* bfc    = (const float*)d_in[11];
    float* out = (float*)d_out;

    k_conv_gemm1s<<<NCONV + NN / 16, 256>>>(ei, x, W1, a_src1, a_dst1); // 0
    k_scan_scatter<<<NBLK, SCAN_B>>>();                                // 1
    k_agg1<<<(NN + 7) / 8, 256>>>(b1);                                 // 2
    k_gemm2s<<<NGB2, 256>>>(W2, a_src2, a_dst2);                       // 3 <- ncu
    k_agg2<<<(NN + 7) / 8, 256>>>(b2, Wfc, bfc, out);                  // 4
}